// round 8
// baseline (speedup 1.0000x reference)
#include <cuda_runtime.h>

// penalty = sum_{b,k} S[b,k] * || P[i_b] - P[j_{b,k}] ||_2
// P [500000,128] f32, i [4096] i32, j [4096,64] i32, S [4096,64] f32 -> scalar f32.
// Single kernel: gather core (R7) + last-block-done publish, self-resetting
// device state so every graph replay performs identical work.

#define B_TOTAL 4096
#define K_NEIGH 64
#define D_DIM   128
#define WPB     4
#define KPU     32              // k's per unit (warp)
#define NGS     (KPU / 4)       // 8 group-sets of 4 rows per unit
#define GWIN    2               // group-sets in flight (8 rows/warp)
#define GRID    ((B_TOTAL * 2) / WPB)   // 2048 blocks
#define FULL    0xFFFFFFFFu

__device__ float        g_accum;   // zero-initialized; reset by last block
__device__ unsigned int g_count;   // zero-initialized; reset by last block

__global__ __launch_bounds__(WPB * 32, 6)
void custom_loss_kernel(const float* __restrict__ P,
                        const int*   __restrict__ i_idx,
                        const int*   __restrict__ j_idx,
                        const float* __restrict__ S,
                        float* __restrict__ out) {
    const int lane = threadIdx.x & 31;
    const int w    = threadIdx.x >> 5;
    const int unit = blockIdx.x * WPB + w;          // 0 .. 8191
    const int b    = unit >> 1;
    const int koff = (unit & 1) << 5;               // 0 or 32
    const int g    = lane >> 3;                     // row group (0..3)
    const int sub  = lane & 7;                      // lane within group

    __shared__ int   sJ[WPB][KPU];
    __shared__ float sS[WPB][KPU];

    // Warp-private coalesced staging.
    sJ[w][lane] = j_idx[b * K_NEIGH + koff + lane];
    sS[w][lane] = S[b * K_NEIGH + koff + lane];
    __syncwarp();

    // Pi slots for this lane (independent of group).
    const unsigned irow = (unsigned)i_idx[b];
    const float4* PiRow = reinterpret_cast<const float4*>(P + irow * (unsigned)D_DIM);
    float4 pi4[4];
    #pragma unroll
    for (int it = 0; it < 4; it++)
        pi4[it] = __ldg(PiRow + sub + 8 * it);

    // Prologue: fill GWIN group-sets (8 rows in flight).
    float4 pj[GWIN][4];
    #pragma unroll
    for (int q = 0; q < GWIN; q++) {
        unsigned jr = (unsigned)sJ[w][4 * q + g];
        const float4* row = reinterpret_cast<const float4*>(P + jr * (unsigned)D_DIM);
        #pragma unroll
        for (int it = 0; it < 4; it++)
            pj[q][it] = __ldg(row + sub + 8 * it);
    }

    float acc = 0.0f;
    #pragma unroll
    for (int gs = 0; gs < NGS; gs++) {
        const int q = gs % GWIN;    // compile-time after full unroll

        float sq = 0.0f;
        #pragma unroll
        for (int it = 0; it < 4; it++) {
            float dx = pi4[it].x - pj[q][it].x;
            float dy = pi4[it].y - pj[q][it].y;
            float dz = pi4[it].z - pj[q][it].z;
            float dw = pi4[it].w - pj[q][it].w;
            sq += dx * dx + dy * dy + dz * dz + dw * dw;
        }

        // Refill slot q immediately.
        if (gs + GWIN < NGS) {
            unsigned jr = (unsigned)sJ[w][4 * (gs + GWIN) + g];
            const float4* row = reinterpret_cast<const float4*>(P + jr * (unsigned)D_DIM);
            #pragma unroll
            for (int it = 0; it < 4; it++)
                pj[q][it] = __ldg(row + sub + 8 * it);
        }

        // Reduce within each 8-lane group (4 rows per 3 shuffles).
        sq += __shfl_xor_sync(FULL, sq, 1);
        sq += __shfl_xor_sync(FULL, sq, 2);
        sq += __shfl_xor_sync(FULL, sq, 4);

        if (sub == 0)
            acc += sqrtf(sq) * sS[w][4 * gs + g];
    }

    // Lanes 0,8,16,24 hold partials; one atomic per warp into device accumulator.
    acc += __shfl_xor_sync(FULL, acc, 8);
    acc += __shfl_xor_sync(FULL, acc, 16);
    if (lane == 0) atomicAdd(&g_accum, acc);

    // Last-block-done: publish result and reset state for the next replay.
    __syncthreads();
    if (threadIdx.x == 0) {
        __threadfence();
        unsigned old = atomicAdd(&g_count, 1u);
        if (old == GRID - 1) {
            __threadfence();            // make all g_accum adds visible
            *out    = g_accum;
            g_accum = 0.0f;             // self-reset: next replay starts clean
            g_count = 0u;
        }
    }
}

extern "C" void kernel_launch(void* const* d_in, const int* in_sizes, int n_in,
                              void* d_out, int out_size) {
    const float* P  = (const float*)d_in[0];
    const int*   ii = (const int*)  d_in[1];
    const int*   jj = (const int*)  d_in[2];
    const float* S  = (const float*)d_in[3];
    float* out = (float*)d_out;

    custom_loss_kernel<<<GRID, WPB * 32>>>(P, ii, jj, S, out);
}

// round 9
// speedup vs baseline: 1.0202x; 1.0202x over previous
#include <cuda_runtime.h>

// penalty = sum_{b,k} S[b,k] * || P[i_b] - P[j_{b,k}] ||_2
// P [500000,128] f32, i [4096] i32, j [4096,64] i32, S [4096,64] f32 -> scalar f32.
// R7 structure (2 kernels, 8192 half-units, rolling 8-rows-in-flight window)
// with Pi moved to shared memory to cut regs and fit 8 blocks/SM (32 warps).

#define B_TOTAL 4096
#define K_NEIGH 64
#define D_DIM   128
#define WPB     4
#define KPU     32              // k's per unit (warp)
#define NGS     (KPU / 4)       // 8 group-sets of 4 rows per unit
#define GWIN    2               // group-sets in flight (8 rows/warp)
#define FULL    0xFFFFFFFFu

__global__ void zero_out_kernel(float* out) { *out = 0.0f; }

__global__ __launch_bounds__(WPB * 32, 8)
void custom_loss_kernel(const float* __restrict__ P,
                        const int*   __restrict__ i_idx,
                        const int*   __restrict__ j_idx,
                        const float* __restrict__ S,
                        float* __restrict__ out) {
    const int lane = threadIdx.x & 31;
    const int w    = threadIdx.x >> 5;
    const int unit = blockIdx.x * WPB + w;          // 0 .. 8191
    const int b    = unit >> 1;
    const int koff = (unit & 1) << 5;               // 0 or 32
    const int g    = lane >> 3;                     // row group (0..3)
    const int sub  = lane & 7;                      // lane within group

    __shared__ int    sJ[WPB][KPU];
    __shared__ float  sS[WPB][KPU];
    __shared__ float4 sPi[WPB][D_DIM / 4];          // Pi row per warp (saves 16 regs)

    // Warp-private coalesced staging.
    sJ[w][lane] = j_idx[b * K_NEIGH + koff + lane];
    sS[w][lane] = S[b * K_NEIGH + koff + lane];
    {
        const unsigned irow = (unsigned)i_idx[b];
        sPi[w][lane] = __ldg(reinterpret_cast<const float4*>(P + irow * (unsigned)D_DIM) + lane);
    }
    __syncwarp();

    // Prologue: fill GWIN group-sets (8 rows in flight per warp).
    float4 pj[GWIN][4];
    #pragma unroll
    for (int q = 0; q < GWIN; q++) {
        unsigned jr = (unsigned)sJ[w][4 * q + g];
        const float4* row = reinterpret_cast<const float4*>(P + jr * (unsigned)D_DIM);
        #pragma unroll
        for (int it = 0; it < 4; it++)
            pj[q][it] = __ldg(row + sub + 8 * it);
    }

    float acc = 0.0f;
    #pragma unroll
    for (int gs = 0; gs < NGS; gs++) {
        const int q = gs % GWIN;    // compile-time after full unroll

        float sq = 0.0f;
        #pragma unroll
        for (int it = 0; it < 4; it++) {
            const float4 pi = sPi[w][sub + 8 * it];   // broadcast LDS, conflict-free
            float dx = pi.x - pj[q][it].x;
            float dy = pi.y - pj[q][it].y;
            float dz = pi.z - pj[q][it].z;
            float dw = pi.w - pj[q][it].w;
            sq += dx * dx + dy * dy + dz * dz + dw * dw;
        }

        // Refill slot q immediately.
        if (gs + GWIN < NGS) {
            unsigned jr = (unsigned)sJ[w][4 * (gs + GWIN) + g];
            const float4* row = reinterpret_cast<const float4*>(P + jr * (unsigned)D_DIM);
            #pragma unroll
            for (int it = 0; it < 4; it++)
                pj[q][it] = __ldg(row + sub + 8 * it);
        }

        // Reduce within each 8-lane group (4 rows per 3 shuffles).
        sq += __shfl_xor_sync(FULL, sq, 1);
        sq += __shfl_xor_sync(FULL, sq, 2);
        sq += __shfl_xor_sync(FULL, sq, 4);

        if (sub == 0)
            acc += sqrtf(sq) * sS[w][4 * gs + g];
    }

    // Lanes 0,8,16,24 hold partials; one atomic per warp.
    acc += __shfl_xor_sync(FULL, acc, 8);
    acc += __shfl_xor_sync(FULL, acc, 16);
    if (lane == 0) atomicAdd(out, acc);
}

extern "C" void kernel_launch(void* const* d_in, const int* in_sizes, int n_in,
                              void* d_out, int out_size) {
    const float* P  = (const float*)d_in[0];
    const int*   ii = (const int*)  d_in[1];
    const int*   jj = (const int*)  d_in[2];
    const float* S  = (const float*)d_in[3];
    float* out = (float*)d_out;

    zero_out_kernel<<<1, 1>>>(out);
    custom_loss_kernel<<<(B_TOTAL * 2) / WPB, WPB * 32>>>(P, ii, jj, S, out);
}